// round 16
// baseline (speedup 1.0000x reference)
#include <cuda_runtime.h>
#include <math.h>

// Problem constants
#define B_    32
#define C_    256
#define CR_   64
#define HW_   12544       // 112*112 floats per channel
#define NCH   (B_*C_)     // 8192 channels

// v8 (32B) tiling: 12544/8 = 1568 = 6*256 + 32
#define NF8   6
#define NT8   32
// float4 tiling: 3136 = 12*256 + 64
#define NF4   12
#define NT4   64

__device__ float    g_gap[NCH];
__device__ float    g_h[B_ * CR_];
__device__ unsigned g_tick[B_];   // +256 per launch each; (tk+1)&255==0 elects one CTA
__device__ unsigned g_rel[B_];    // +1 per launch (release counter, never reset)

struct F8 { float4 a, b; };

__device__ __forceinline__ F8 ld_evict_last8(const float* p) {
    unsigned r0,r1,r2,r3,r4,r5,r6,r7;
    asm("ld.global.L2::evict_last.v8.b32 {%0,%1,%2,%3,%4,%5,%6,%7}, [%8];"
        : "=r"(r0),"=r"(r1),"=r"(r2),"=r"(r3),
          "=r"(r4),"=r"(r5),"=r"(r6),"=r"(r7) : "l"(p));
    F8 v;
    v.a.x = __uint_as_float(r0); v.a.y = __uint_as_float(r1);
    v.a.z = __uint_as_float(r2); v.a.w = __uint_as_float(r3);
    v.b.x = __uint_as_float(r4); v.b.y = __uint_as_float(r5);
    v.b.z = __uint_as_float(r6); v.b.w = __uint_as_float(r7);
    return v;
}

// ---------------------------------------------------------------------------
// Fused SE kernel: one CTA per (b,c) channel does
//   1. GAP of its channel (evict_last: pin the 50KB in L2)
//   2. per-batch ticket; last CTA of batch computes hidden layer h[b,:]
//      and bumps the batch release counter
//   3. all CTAs of the batch: spin on release (streaming loads already in
//      flight), compute own gate per-warp, scale own channel (L2-hot reads)
// Deadlock-safe: blocks dispatch in ascending order; 4 CTAs/SM forced ->
// 592 resident >= 2 full batches, so the oldest incomplete batch always
// becomes fully resident and completes.
// ---------------------------------------------------------------------------
__global__ __launch_bounds__(256, 4) void se_fused(
    const float* __restrict__ x,
    const float* __restrict__ w1, const float* __restrict__ b1,
    const float* __restrict__ w2, const float* __restrict__ b2,
    float* __restrict__ out) {
    const int bc = blockIdx.x;
    const int b  = bc >> 8;          // batch (C_ == 256)
    const int c  = bc & 255;         // channel within batch
    const int t  = threadIdx.x;

    // snapshot release counter BEFORE our arrival -> release of this launch
    // is guaranteed to happen after this read (it needs our ticket).
    const unsigned rel0 = *(volatile const unsigned*)(g_rel + b);

    // ---- Stage 1: GAP (pin channel lines in L2) ----
    const float* __restrict__ base = x + (size_t)bc * HW_;
    {
        F8 v[NF8];
        #pragma unroll
        for (int k = 0; k < NF8; ++k)
            v[k] = ld_evict_last8(base + (t + k * 256) * 8);
        F8 vt;
        if (t < NT8) vt = ld_evict_last8(base + (t + NF8 * 256) * 8);

        float sum = 0.0f;
        #pragma unroll
        for (int k = 0; k < NF8; ++k)
            sum += ((v[k].a.x + v[k].a.y) + (v[k].a.z + v[k].a.w))
                 + ((v[k].b.x + v[k].b.y) + (v[k].b.z + v[k].b.w));
        if (t < NT8)
            sum += ((vt.a.x + vt.a.y) + (vt.a.z + vt.a.w))
                 + ((vt.b.x + vt.b.y) + (vt.b.z + vt.b.w));

        #pragma unroll
        for (int o = 16; o > 0; o >>= 1)
            sum += __shfl_xor_sync(0xFFFFFFFFu, sum, o);

        __shared__ float s[8];
        if ((t & 31) == 0) s[t >> 5] = sum;
        __syncthreads();
        if (t < 8) {
            sum = s[t];
            #pragma unroll
            for (int o = 4; o > 0; o >>= 1)
                sum += __shfl_xor_sync(0xFFu, sum, o);
            if (t == 0)
                g_gap[bc] = sum * (1.0f / (float)HW_);
        }
    }

    // ---- Stage 2: arrival ticket; elected CTA computes h[b,:] ----
    __shared__ unsigned last_sh;
    if (t == 0) {
        __threadfence();                              // publish g_gap[bc]
        unsigned tk = atomicAdd(&g_tick[b], 1u);
        last_sh = (((tk + 1u) & 255u) == 0u) ? 1u : 0u;
    }
    __syncthreads();

    if (last_sh) {
        __threadfence();  // acquire all g_gap of this batch
        __shared__ float gap_s[C_];
        const volatile float* gg = (const volatile float*)g_gap + b * C_;
        gap_s[t] = gg[t];
        __syncthreads();
        if (t < CR_) {
            float acc = b1[t];
            const float* __restrict__ w = w1 + t * C_;
            #pragma unroll 8
            for (int cc = 0; cc < C_; ++cc) acc = fmaf(gap_s[cc], w[cc], acc);
            g_h[b * CR_ + t] = fmaxf(acc, 0.0f);
        }
        __syncthreads();
        if (t == 0) {
            __threadfence();                 // publish g_h[b,:]
            atomicAdd(&g_rel[b], 1u);        // release the batch
        }
    }

    // ---- Stage 3: issue streaming loads (L2-hot), then wait for release ----
    const float4* __restrict__ xp =
        reinterpret_cast<const float4*>(x + (size_t)bc * HW_);
    float4* __restrict__ op =
        reinterpret_cast<float4*>(out + (size_t)bc * HW_);

    float4 v[NF4];
    #pragma unroll
    for (int k = 0; k < NF4; ++k)
        v[k] = __ldlu(xp + t + k * 256);
    float4 vt;
    if (t < NT4) vt = __ldlu(xp + t + NF4 * 256);

    while (*(volatile const unsigned*)(g_rel + b) == rel0)
        __nanosleep(64);
    __threadfence();  // acquire g_h

    // ---- per-warp gate: all lanes end with the same value (xor-reduce) ----
    const int lane = t & 31;
    float acc;
    {
        const volatile float* hp = (const volatile float*)g_h + b * CR_;
        const float* __restrict__ w = w2 + c * CR_;
        acc = fmaf(hp[lane], w[lane], fmaf(hp[lane + 32], w[lane + 32], 0.0f));
        #pragma unroll
        for (int o = 16; o > 0; o >>= 1)
            acc += __shfl_xor_sync(0xFFFFFFFFu, acc, o);
    }
    const float g = 1.0f / (1.0f + __expf(-(acc + b2[c])));

    // ---- scale + streaming stores ----
    #pragma unroll
    for (int k = 0; k < NF4; ++k) {
        v[k].x *= g; v[k].y *= g; v[k].z *= g; v[k].w *= g;
        __stcs(op + t + k * 256, v[k]);
    }
    if (t < NT4) {
        vt.x *= g; vt.y *= g; vt.z *= g; vt.w *= g;
        __stcs(op + t + NF4 * 256, vt);
    }
}

// ---------------------------------------------------------------------------
extern "C" void kernel_launch(void* const* d_in, const int* in_sizes, int n_in,
                              void* d_out, int out_size) {
    const float* x  = (const float*)d_in[0];
    const float* w1 = (const float*)d_in[1];
    const float* b1 = (const float*)d_in[2];
    const float* w2 = (const float*)d_in[3];
    const float* b2 = (const float*)d_in[4];
    float* out = (float*)d_out;

    se_fused<<<NCH, 256>>>(x, w1, b1, w2, b2, out);
}

// round 17
// speedup vs baseline: 4.0604x; 4.0604x over previous
#include <cuda_runtime.h>
#include <math.h>

// Problem constants
#define B_    32
#define C_    256
#define CR_   64
#define HW_   12544       // 112*112 floats per channel
#define NCH   (B_*C_)     // 8192 channels
#define KEEP  2048        // tail channels pinned in L2 (~103 MB)

// v8 (32B) tiling: 12544/8 = 1568 = 6*256 + 32
#define NF8   6
#define NT8   32
// float4 tiling: 3136 = 12*256 + 64
#define NF4   12
#define NT4   64

__device__ float    g_gap[NCH];
__device__ float    g_h[B_ * CR_];
__device__ unsigned g_tick[B_];   // +256 per launch each; (tk+1)&255==0 elects one CTA

struct F8 { float4 a, b; };

__device__ __forceinline__ F8 ld_evict_last8(const float* p) {
    unsigned r0,r1,r2,r3,r4,r5,r6,r7;
    asm("ld.global.L2::evict_last.v8.b32 {%0,%1,%2,%3,%4,%5,%6,%7}, [%8];"
        : "=r"(r0),"=r"(r1),"=r"(r2),"=r"(r3),
          "=r"(r4),"=r"(r5),"=r"(r6),"=r"(r7) : "l"(p));
    F8 v;
    v.a.x = __uint_as_float(r0); v.a.y = __uint_as_float(r1);
    v.a.z = __uint_as_float(r2); v.a.w = __uint_as_float(r3);
    v.b.x = __uint_as_float(r4); v.b.y = __uint_as_float(r5);
    v.b.z = __uint_as_float(r6); v.b.w = __uint_as_float(r7);
    return v;
}

__device__ __forceinline__ F8 ld_evict_first8(const float* p) {
    unsigned r0,r1,r2,r3,r4,r5,r6,r7;
    asm("ld.global.L2::evict_first.v8.b32 {%0,%1,%2,%3,%4,%5,%6,%7}, [%8];"
        : "=r"(r0),"=r"(r1),"=r"(r2),"=r"(r3),
          "=r"(r4),"=r"(r5),"=r"(r6),"=r"(r7) : "l"(p));
    F8 v;
    v.a.x = __uint_as_float(r0); v.a.y = __uint_as_float(r1);
    v.a.z = __uint_as_float(r2); v.a.w = __uint_as_float(r3);
    v.b.x = __uint_as_float(r4); v.b.y = __uint_as_float(r5);
    v.b.z = __uint_as_float(r6); v.b.w = __uint_as_float(r7);
    return v;
}

// ---------------------------------------------------------------------------
// Kernel 1: GAP + per-batch hidden layer. One CTA per channel; 32B loads;
// tail channels pinned in L2. Last CTA of each batch (ticket) computes h[b,:].
// Each CTA signals launch_dependents as soon as it can no longer produce
// data the scale kernel consumes (PDL overlap of GAP drain with scale ramp).
// ---------------------------------------------------------------------------
__global__ __launch_bounds__(256) void gap_kernel(
    const float* __restrict__ x,
    const float* __restrict__ w1, const float* __restrict__ b1) {
    const int bc = blockIdx.x;
    const int b  = bc >> 8;          // batch index (C_ == 256)
    const int t  = threadIdx.x;
    const float* __restrict__ base = x + (size_t)bc * HW_;
    const bool keep = (bc >= NCH - KEEP);

    F8 v[NF8];
    F8 vt;
    if (keep) {
        #pragma unroll
        for (int k = 0; k < NF8; ++k)
            v[k] = ld_evict_last8(base + (t + k * 256) * 8);
        if (t < NT8) vt = ld_evict_last8(base + (t + NF8 * 256) * 8);
    } else {
        #pragma unroll
        for (int k = 0; k < NF8; ++k)
            v[k] = ld_evict_first8(base + (t + k * 256) * 8);
        if (t < NT8) vt = ld_evict_first8(base + (t + NF8 * 256) * 8);
    }

    float sum = 0.0f;
    #pragma unroll
    for (int k = 0; k < NF8; ++k)
        sum += ((v[k].a.x + v[k].a.y) + (v[k].a.z + v[k].a.w))
             + ((v[k].b.x + v[k].b.y) + (v[k].b.z + v[k].b.w));
    if (t < NT8)
        sum += ((vt.a.x + vt.a.y) + (vt.a.z + vt.a.w))
             + ((vt.b.x + vt.b.y) + (vt.b.z + vt.b.w));

    #pragma unroll
    for (int o = 16; o > 0; o >>= 1)
        sum += __shfl_xor_sync(0xFFFFFFFFu, sum, o);

    __shared__ float s[8];
    __shared__ unsigned last_sh;
    if ((t & 31) == 0) s[t >> 5] = sum;
    __syncthreads();
    if (t < 8) {
        sum = s[t];
        #pragma unroll
        for (int o = 4; o > 0; o >>= 1)
            sum += __shfl_xor_sync(0xFFu, sum, o);
        if (t == 0)
            g_gap[bc] = sum * (1.0f / (float)HW_);
    }

    // ---- per-batch last-CTA election (exactly 256 arrivals per launch) ----
    if (t == 0) {
        __threadfence();                              // publish g_gap[bc]
        unsigned tk = atomicAdd(&g_tick[b], 1u);
        last_sh = (((tk + 1u) & 255u) == 0u) ? 1u : 0u;
    }
    __syncthreads();
    if (!last_sh) {
        // this CTA produces nothing more the dependent kernel needs
        asm volatile("griddepcontrol.launch_dependents;" ::: "memory");
        return;
    }

    // ---- elected CTA: hidden layer h[b, 0:64] ----
    __threadfence();  // acquire: see all g_gap writes of this batch
    __shared__ float gap_s[C_];
    const volatile float* gg = (const volatile float*)g_gap + b * C_;
    gap_s[t] = gg[t];
    __syncthreads();

    if (t < CR_) {
        float acc = b1[t];
        const float* __restrict__ w = w1 + t * C_;
        #pragma unroll 8
        for (int c = 0; c < C_; ++c) acc = fmaf(gap_s[c], w[c], acc);
        g_h[b * CR_ + t] = fmaxf(acc, 0.0f);
    }
    __syncthreads();
    __threadfence();  // publish g_h before signaling dependents
    asm volatile("griddepcontrol.launch_dependents;" ::: "memory");
}

// ---------------------------------------------------------------------------
// Kernel 2 (PDL dependent): out = x * gate[bc]. One CTA per channel, reverse
// order (pinned tail first). Streaming x-loads are issued BEFORE the grid
// dependency wait (they depend only on the read-only input x); the gate
// dot-product reads g_h only after griddepcontrol.wait.
// ---------------------------------------------------------------------------
__global__ __launch_bounds__(256) void scale_kernel(
    const float* __restrict__ x, float* __restrict__ out,
    const float* __restrict__ w2, const float* __restrict__ b2) {
    const int bc = NCH - 1 - (int)blockIdx.x;   // reverse order
    const int b  = bc >> 8;
    const int c  = bc & 255;
    const int t  = threadIdx.x;

    const float4* __restrict__ xp =
        reinterpret_cast<const float4*>(x + (size_t)bc * HW_);
    float4* __restrict__ op =
        reinterpret_cast<float4*>(out + (size_t)bc * HW_);

    // ---- 1. issue all streaming loads (independent of primary grid) ----
    float4 v[NF4];
    #pragma unroll
    for (int k = 0; k < NF4; ++k)
        v[k] = __ldlu(xp + t + k * 256);
    float4 vt;
    if (t < NT4) vt = __ldlu(xp + t + NF4 * 256);

    // ---- 2. wait for primary grid (g_h visible afterwards) ----
    asm volatile("griddepcontrol.wait;" ::: "memory");

    // ---- 3. gate dot-product (warp 0) ----
    __shared__ float gsh;
    if (t < 32) {
        const float* __restrict__ hp = g_h + b * CR_;
        const float* __restrict__ w  = w2 + c * CR_;
        float acc = fmaf(hp[t], w[t], fmaf(hp[t + 32], w[t + 32], 0.0f));
        #pragma unroll
        for (int o = 16; o > 0; o >>= 1)
            acc += __shfl_xor_sync(0xFFFFFFFFu, acc, o);
        if (t == 0)
            gsh = 1.0f / (1.0f + __expf(-(acc + b2[c])));
    }
    __syncthreads();
    const float g = gsh;

    // ---- 4. scale + streaming stores ----
    #pragma unroll
    for (int k = 0; k < NF4; ++k) {
        v[k].x *= g; v[k].y *= g; v[k].z *= g; v[k].w *= g;
        __stcs(op + t + k * 256, v[k]);
    }
    if (t < NT4) {
        vt.x *= g; vt.y *= g; vt.z *= g; vt.w *= g;
        __stcs(op + t + NF4 * 256, vt);
    }
}

// ---------------------------------------------------------------------------
extern "C" void kernel_launch(void* const* d_in, const int* in_sizes, int n_in,
                              void* d_out, int out_size) {
    const float* x  = (const float*)d_in[0];
    const float* w1 = (const float*)d_in[1];
    const float* b1 = (const float*)d_in[2];
    const float* w2 = (const float*)d_in[3];
    const float* b2 = (const float*)d_in[4];
    float* out = (float*)d_out;

    gap_kernel<<<NCH, 256>>>(x, w1, b1);

    // Dependent launch with programmatic stream serialization (PDL)
    cudaLaunchConfig_t cfg = {};
    cfg.gridDim  = dim3(NCH, 1, 1);
    cfg.blockDim = dim3(256, 1, 1);
    cfg.dynamicSmemBytes = 0;
    cfg.stream = 0;
    cudaLaunchAttribute attrs[1];
    attrs[0].id = cudaLaunchAttributeProgrammaticStreamSerialization;
    attrs[0].val.programmaticStreamSerializationAllowed = 1;
    cfg.attrs = attrs;
    cfg.numAttrs = 1;
    cudaLaunchKernelEx(&cfg, scale_kernel, x, out, w2, b2);
}